// round 8
// baseline (speedup 1.0000x reference)
#include <cuda_runtime.h>

// Problem constants (fixed by the dataset)
#define B_ 8
#define S_ 128
#define D_ 480
#define E_ 8
#define C_ 10
#define F_ 994    // W row stride

// Per-row precomputed contributions.
// Cj[b,s,k]: node1 (W cols 0:480) + edge_i (W cols 960:968), keyed by j
// Ci[b,s,k]: node2 (W cols 480:960) + edge_j (W cols 968:976) + bias, keyed by i
__device__ float g_Cj[B_ * S_ * C_];
__device__ float g_Ci[B_ * S_ * C_];

typedef unsigned long long u64;

// ---- packed fp32x2 helpers (sm_103a FFMA2 path, PTX-only) -------------------
__device__ __forceinline__ u64 pack2(float lo, float hi) {
    u64 r; asm("mov.b64 %0, {%1, %2};" : "=l"(r) : "f"(lo), "f"(hi)); return r;
}
__device__ __forceinline__ void unpack2(u64 v, float& lo, float& hi) {
    asm("mov.b64 {%0, %1}, %2;" : "=f"(lo), "=f"(hi) : "l"(v));
}
__device__ __forceinline__ u64 fma2(u64 a, u64 b, u64 c) {
    u64 d; asm("fma.rn.f32x2 %0, %1, %2, %3;" : "=l"(d) : "l"(a), "l"(b), "l"(c)); return d;
}
__device__ __forceinline__ u64 add2(u64 a, u64 b) {
    u64 d; asm("add.rn.f32x2 %0, %1, %2;" : "=l"(d) : "l"(a), "l"(b)); return d;
}

// ---------------------------------------------------------------------------
// Kernel 1: 256 blocks x 256 threads, 4 rows/block, one warp per (row, part).
// gcn via float4 (16B-aligned rows); W via LDG.64 (rows only 8B-aligned).
// ---------------------------------------------------------------------------
__global__ __launch_bounds__(256)
void precompute_rows(const float* __restrict__ gcn,
                     const float* __restrict__ wp,
                     const float* __restrict__ W,
                     const float* __restrict__ bias) {
    int t = threadIdx.x;
    int warp = t >> 5, lane = t & 31;
    int row = blockIdx.x * 4 + (warp >> 1);   // 1024 rows total
    int part = warp & 1;                       // 0: Cj (cols 0:480), 1: Ci (480:960)
    const float* g = gcn + (size_t)row * D_;
    const float* Wb = W + part * 480;

    u64 acc[C_];
#pragma unroll
    for (int k = 0; k < C_; k++) acc[k] = 0ull;

#pragma unroll
    for (int it = 0; it < 3; it++) {           // d = 0..383
        int d = it * 128 + lane * 4;
        float4 gv = *reinterpret_cast<const float4*>(g + d);
        u64 gl = pack2(gv.x, gv.y), gh = pack2(gv.z, gv.w);
#pragma unroll
        for (int k = 0; k < C_; k++) {
            const float* wr = Wb + k * F_ + d;
            acc[k] = fma2(gl, *reinterpret_cast<const u64*>(wr), acc[k]);
            acc[k] = fma2(gh, *reinterpret_cast<const u64*>(wr + 2), acc[k]);
        }
    }
    if (lane < 24) {                           // d = 384..479
        int d = 384 + lane * 4;
        float4 gv = *reinterpret_cast<const float4*>(g + d);
        u64 gl = pack2(gv.x, gv.y), gh = pack2(gv.z, gv.w);
#pragma unroll
        for (int k = 0; k < C_; k++) {
            const float* wr = Wb + k * F_ + d;
            acc[k] = fma2(gl, *reinterpret_cast<const u64*>(wr), acc[k]);
            acc[k] = fma2(gh, *reinterpret_cast<const u64*>(wr + 2), acc[k]);
        }
    }

    float s[C_];
#pragma unroll
    for (int k = 0; k < C_; k++) { float lo, hi; unpack2(acc[k], lo, hi); s[k] = lo + hi; }
#pragma unroll
    for (int k = 0; k < C_; k++)
#pragma unroll
        for (int off = 16; off > 0; off >>= 1)
            s[k] += __shfl_down_sync(0xffffffffu, s[k], off);

    if (lane == 0) {
        int b = row >> 7, si = row & (S_ - 1);
        const float* ed = wp + (((size_t)(b * S_ + si) * S_) + si) * E_;
        float e0[E_];
#pragma unroll
        for (int e = 0; e < E_; e++) e0[e] = ed[e];
        if (part == 0) {
#pragma unroll
            for (int k = 0; k < C_; k++) {
                float v = s[k];
#pragma unroll
                for (int e = 0; e < E_; e++) v += e0[e] * W[k * F_ + 960 + e];
                g_Cj[row * C_ + k] = v;
            }
        } else {
#pragma unroll
            for (int k = 0; k < C_; k++) {
                float v = s[k] + bias[k];
#pragma unroll
                for (int e = 0; e < E_; e++) v += e0[e] * W[k * F_ + 968 + e];
                g_Ci[row * C_ + k] = v;
            }
        }
    }
}

// ---------------------------------------------------------------------------
// Kernel 2: 512 blocks x 128 threads. Block = i-row pair (bi0, bi0+1) of one
// batch; thread t = column j, computing pixels (i0,j) and (i1,j).
// Weights (90 u64) live in smem, each LDS.64 feeds both pixels. Cj[b,j] is
// shared by the pair (one set of 5 loads). All feature/output traffic is
// direct global (fully-covered strided) — no staging, no scatter, one barrier.
// ---------------------------------------------------------------------------
__global__ __launch_bounds__(128)
void combine_kernel(const float* __restrict__ label,
                    const float* __restrict__ wp,
                    const float* __restrict__ W,
                    float* __restrict__ out) {
    __shared__ u64 sWw[18][5];   // f<8: wp col 976+f; f>=8: label col 984+(f-8)

    int t = threadIdx.x;
    if (t < 90) {
        int f = t / 5, h = t - 5 * f;
        int col = (f < 8) ? (976 + f) : (984 + (f - 8));
        sWw[f][h] = pack2(W[(2 * h) * F_ + col], W[(2 * h + 1) * F_ + col]);
    }
    __syncthreads();

    int bi0 = blockIdx.x * 2;        // first (b,i) row; pair stays in-batch
    int b  = bi0 >> 7;
    int i0 = bi0 & (S_ - 1);
    int i1 = i0 + 1;
    int j  = t;
    size_t p0 = (size_t)bi0 * S_ + j;
    size_t p1 = p0 + S_;

    // ---- features: direct global loads (fully covered, L2-resident)
    float f0[18], f1[18];
    {
        const float4* q0 = reinterpret_cast<const float4*>(wp + p0 * E_);
        const float4* q1 = reinterpret_cast<const float4*>(wp + p1 * E_);
        float4 a = q0[0], c = q0[1];
        f0[0] = a.x; f0[1] = a.y; f0[2] = a.z; f0[3] = a.w;
        f0[4] = c.x; f0[5] = c.y; f0[6] = c.z; f0[7] = c.w;
        a = q1[0]; c = q1[1];
        f1[0] = a.x; f1[1] = a.y; f1[2] = a.z; f1[3] = a.w;
        f1[4] = c.x; f1[5] = c.y; f1[6] = c.z; f1[7] = c.w;
    }
    {
        const float2* q0 = reinterpret_cast<const float2*>(label + p0 * C_);
        const float2* q1 = reinterpret_cast<const float2*>(label + p1 * C_);
#pragma unroll
        for (int h = 0; h < 5; h++) {
            float2 v0 = q0[h], v1 = q1[h];
            f0[8 + 2 * h] = v0.x; f0[9 + 2 * h] = v0.y;
            f1[8 + 2 * h] = v1.x; f1[9 + 2 * h] = v1.y;
        }
    }
    // masks: label ch 1..3 (f=9..11) kept when j>=i; ch 4..9 (f=12..17) when i>=j
    {
        float mu0 = (j >= i0) ? 1.f : 0.f, ml0 = (i0 >= j) ? 1.f : 0.f;
        float mu1 = (j >= i1) ? 1.f : 0.f, ml1 = (i1 >= j) ? 1.f : 0.f;
        f0[9] *= mu0; f0[10] *= mu0; f0[11] *= mu0;
        f1[9] *= mu1; f1[10] *= mu1; f1[11] *= mu1;
#pragma unroll
        for (int f = 12; f < 18; f++) { f0[f] *= ml0; f1[f] *= ml1; }
    }

    // ---- init accumulators: Cj shared by the pair; Ci per row (broadcast)
    u64 A0[5], A1[5];
    {
        const u64* cj  = reinterpret_cast<const u64*>(g_Cj + (b * S_ + j) * C_);
        const u64* ci0 = reinterpret_cast<const u64*>(g_Ci + bi0 * C_);
        const u64* ci1 = reinterpret_cast<const u64*>(g_Ci + (bi0 + 1) * C_);
#pragma unroll
        for (int h = 0; h < 5; h++) {
            u64 cjv = cj[h];
            A0[h] = add2(cjv, ci0[h]);
            A1[h] = add2(cjv, ci1[h]);
        }
    }

    // ---- 18 features x 5 channel pairs; each weight LDS.64 feeds both pixels
#pragma unroll
    for (int f = 0; f < 18; f++) {
        u64 v0 = pack2(f0[f], f0[f]);
        u64 v1 = pack2(f1[f], f1[f]);
#pragma unroll
        for (int h = 0; h < 5; h++) {
            u64 w = sWw[f][h];
            A0[h] = fma2(v0, w, A0[h]);
            A1[h] = fma2(v1, w, A1[h]);
        }
    }

    // ---- direct stores (fully covered strided)
    u64* o0 = reinterpret_cast<u64*>(out + p0 * C_);
    u64* o1 = reinterpret_cast<u64*>(out + p1 * C_);
#pragma unroll
    for (int h = 0; h < 5; h++) { o0[h] = A0[h]; o1[h] = A1[h]; }
}

extern "C" void kernel_launch(void* const* d_in, const int* in_sizes, int n_in,
                              void* d_out, int out_size) {
    const float* gcn   = (const float*)d_in[0];   // [8,128,480]
    const float* label = (const float*)d_in[1];   // [8,128,128,10]
    const float* wp    = (const float*)d_in[2];   // [8,128,128,8]
    // d_in[3] = tensor_masks (all ones, no effect on the reference math)
    const float* W     = (const float*)d_in[4];   // [10,994]
    const float* bias  = (const float*)d_in[5];   // [10]
    float* out = (float*)d_out;                   // [8,128,128,10]

    precompute_rows<<<B_ * S_ / 4, 256>>>(gcn, wp, W, bias);
    combine_kernel<<<B_ * S_ / 2, 128>>>(label, wp, W, out);
}

// round 9
// speedup vs baseline: 1.0269x; 1.0269x over previous
#include <cuda_runtime.h>

// Problem constants (fixed by the dataset)
#define B_ 8
#define S_ 128
#define D_ 480
#define E_ 8
#define C_ 10
#define F_ 994    // W row stride

// Per-row precomputed contributions.
// Cj[b,s,k]: node1 (W cols 0:480) + edge_i (W cols 960:968), keyed by j
// Ci[b,s,k]: node2 (W cols 480:960) + edge_j (W cols 968:976) + bias, keyed by i
__device__ float g_Cj[B_ * S_ * C_];
__device__ float g_Ci[B_ * S_ * C_];

typedef unsigned long long u64;

// ---- packed fp32x2 helpers (sm_103a FFMA2 path, PTX-only) -------------------
__device__ __forceinline__ u64 pack2(float lo, float hi) {
    u64 r; asm("mov.b64 %0, {%1, %2};" : "=l"(r) : "f"(lo), "f"(hi)); return r;
}
__device__ __forceinline__ void unpack2(u64 v, float& lo, float& hi) {
    asm("mov.b64 {%0, %1}, %2;" : "=f"(lo), "=f"(hi) : "l"(v));
}
__device__ __forceinline__ u64 fma2(u64 a, u64 b, u64 c) {
    u64 d; asm("fma.rn.f32x2 %0, %1, %2, %3;" : "=l"(d) : "l"(a), "l"(b), "l"(c)); return d;
}
__device__ __forceinline__ u64 add2(u64 a, u64 b) {
    u64 d; asm("add.rn.f32x2 %0, %1, %2;" : "=l"(d) : "l"(a), "l"(b)); return d;
}

// ---------------------------------------------------------------------------
// Kernel 1: 256 blocks x 256 threads, 4 rows/block, one warp per (row, part).
// gcn via float4 (16B-aligned rows); W via LDG.64 (rows only 8B-aligned).
// ---------------------------------------------------------------------------
__global__ __launch_bounds__(256)
void precompute_rows(const float* __restrict__ gcn,
                     const float* __restrict__ wp,
                     const float* __restrict__ W,
                     const float* __restrict__ bias) {
    int t = threadIdx.x;
    int warp = t >> 5, lane = t & 31;
    int row = blockIdx.x * 4 + (warp >> 1);   // 1024 rows total
    int part = warp & 1;                       // 0: Cj (cols 0:480), 1: Ci (480:960)
    const float* g = gcn + (size_t)row * D_;
    const float* Wb = W + part * 480;

    u64 acc[C_];
#pragma unroll
    for (int k = 0; k < C_; k++) acc[k] = 0ull;

#pragma unroll
    for (int it = 0; it < 3; it++) {           // d = 0..383
        int d = it * 128 + lane * 4;
        float4 gv = *reinterpret_cast<const float4*>(g + d);
        u64 gl = pack2(gv.x, gv.y), gh = pack2(gv.z, gv.w);
#pragma unroll
        for (int k = 0; k < C_; k++) {
            const float* wr = Wb + k * F_ + d;
            acc[k] = fma2(gl, *reinterpret_cast<const u64*>(wr), acc[k]);
            acc[k] = fma2(gh, *reinterpret_cast<const u64*>(wr + 2), acc[k]);
        }
    }
    if (lane < 24) {                           // d = 384..479
        int d = 384 + lane * 4;
        float4 gv = *reinterpret_cast<const float4*>(g + d);
        u64 gl = pack2(gv.x, gv.y), gh = pack2(gv.z, gv.w);
#pragma unroll
        for (int k = 0; k < C_; k++) {
            const float* wr = Wb + k * F_ + d;
            acc[k] = fma2(gl, *reinterpret_cast<const u64*>(wr), acc[k]);
            acc[k] = fma2(gh, *reinterpret_cast<const u64*>(wr + 2), acc[k]);
        }
    }

    float s[C_];
#pragma unroll
    for (int k = 0; k < C_; k++) { float lo, hi; unpack2(acc[k], lo, hi); s[k] = lo + hi; }
#pragma unroll
    for (int k = 0; k < C_; k++)
#pragma unroll
        for (int off = 16; off > 0; off >>= 1)
            s[k] += __shfl_down_sync(0xffffffffu, s[k], off);

    if (lane == 0) {
        int b = row >> 7, si = row & (S_ - 1);
        const float* ed = wp + (((size_t)(b * S_ + si) * S_) + si) * E_;
        float e0[E_];
#pragma unroll
        for (int e = 0; e < E_; e++) e0[e] = ed[e];
        if (part == 0) {
#pragma unroll
            for (int k = 0; k < C_; k++) {
                float v = s[k];
#pragma unroll
                for (int e = 0; e < E_; e++) v += e0[e] * W[k * F_ + 960 + e];
                g_Cj[row * C_ + k] = v;
            }
        } else {
#pragma unroll
            for (int k = 0; k < C_; k++) {
                float v = s[k] + bias[k];
#pragma unroll
                for (int e = 0; e < E_; e++) v += e0[e] * W[k * F_ + 968 + e];
                g_Ci[row * C_ + k] = v;
            }
        }
    }
}

// ---------------------------------------------------------------------------
// Kernel 2: 1024 blocks x 256 threads = 8192 warps (~55/SM). Block = one
// (b,i) row; thread = (pixel j, channel-half). Half 0 computes channel pairs
// {0,1,2}, half 1 pairs {3,4}. All feature/Cj/Ci/output traffic is direct
// global (fully-covered strided, L2-resident); only 90 weight u64 in smem.
// ---------------------------------------------------------------------------
template <int H0, int NH>
__device__ __forceinline__ void combine_half(
    const u64 (*sWw)[5],
    const float* __restrict__ label, const float* __restrict__ wp,
    float* __restrict__ out, int b, int bi, int i, int j, size_t pix)
{
    // independent global loads first (MLP)
    u64 A[NH];
    {
        const u64* cj = reinterpret_cast<const u64*>(g_Cj + (b * S_ + j) * C_) + H0;
        const u64* ci = reinterpret_cast<const u64*>(g_Ci + bi * C_) + H0;
#pragma unroll
        for (int h = 0; h < NH; h++) A[h] = add2(cj[h], ci[h]);
    }
    float f[18];
    {
        const float4* q = reinterpret_cast<const float4*>(wp + pix * E_);
        float4 a = q[0], c = q[1];
        f[0] = a.x; f[1] = a.y; f[2] = a.z; f[3] = a.w;
        f[4] = c.x; f[5] = c.y; f[6] = c.z; f[7] = c.w;
    }
    {
        const float2* q = reinterpret_cast<const float2*>(label + pix * C_);
#pragma unroll
        for (int h = 0; h < 5; h++) {
            float2 v = q[h];
            f[8 + 2 * h] = v.x; f[9 + 2 * h] = v.y;
        }
    }
    // masks: label ch 1..3 (f=9..11) kept when j>=i; ch 4..9 (f=12..17) when i>=j
    float mu = (j >= i) ? 1.f : 0.f;
    float ml = (i >= j) ? 1.f : 0.f;
    f[9] *= mu; f[10] *= mu; f[11] *= mu;
#pragma unroll
    for (int q = 12; q < 18; q++) f[q] *= ml;

#pragma unroll
    for (int q = 0; q < 18; q++) {
        u64 v = pack2(f[q], f[q]);
#pragma unroll
        for (int h = 0; h < NH; h++) A[h] = fma2(v, sWw[q][H0 + h], A[h]);
    }

    u64* o = reinterpret_cast<u64*>(out + pix * C_) + H0;
#pragma unroll
    for (int h = 0; h < NH; h++) o[h] = A[h];
}

__global__ __launch_bounds__(256)
void combine_kernel(const float* __restrict__ label,
                    const float* __restrict__ wp,
                    const float* __restrict__ W,
                    float* __restrict__ out) {
    __shared__ u64 sWw[18][5];   // f<8: wp col 976+f; f>=8: label col 984+(f-8)

    int t = threadIdx.x;
    if (t < 90) {
        int f = t / 5, h = t - 5 * f;
        int col = (f < 8) ? (976 + f) : (984 + (f - 8));
        sWw[f][h] = pack2(W[(2 * h) * F_ + col], W[(2 * h + 1) * F_ + col]);
    }
    __syncthreads();

    int bi = blockIdx.x;             // b*S + i
    int b = bi >> 7;
    int i = bi & (S_ - 1);
    int j = t & (S_ - 1);
    int half = t >> 7;
    size_t pix = (size_t)bi * S_ + j;

    if (half == 0) combine_half<0, 3>(sWw, label, wp, out, b, bi, i, j, pix);
    else           combine_half<3, 2>(sWw, label, wp, out, b, bi, i, j, pix);
}

extern "C" void kernel_launch(void* const* d_in, const int* in_sizes, int n_in,
                              void* d_out, int out_size) {
    const float* gcn   = (const float*)d_in[0];   // [8,128,480]
    const float* label = (const float*)d_in[1];   // [8,128,128,10]
    const float* wp    = (const float*)d_in[2];   // [8,128,128,8]
    // d_in[3] = tensor_masks (all ones, no effect on the reference math)
    const float* W     = (const float*)d_in[4];   // [10,994]
    const float* bias  = (const float*)d_in[5];   // [10]
    float* out = (float*)d_out;                   // [8,128,128,10]

    precompute_rows<<<B_ * S_ / 4, 256>>>(gcn, wp, W, bias);
    combine_kernel<<<B_ * S_, 256>>>(label, wp, W, out);
}

// round 10
// speedup vs baseline: 1.1359x; 1.1062x over previous
#include <cuda_runtime.h>
#include <cstdint>

// Problem constants (fixed by the dataset)
#define B_ 8
#define S_ 128
#define D_ 480
#define E_ 8
#define C_ 10
#define F_ 994    // W row stride

// Per-row precomputed contributions.
__device__ float g_Cj[B_ * S_ * C_];
__device__ float g_Ci[B_ * S_ * C_];

typedef unsigned long long u64;

// ---- packed fp32x2 helpers (sm_103a FFMA2 path, PTX-only) -------------------
__device__ __forceinline__ u64 pack2(float lo, float hi) {
    u64 r; asm("mov.b64 %0, {%1, %2};" : "=l"(r) : "f"(lo), "f"(hi)); return r;
}
__device__ __forceinline__ void unpack2(u64 v, float& lo, float& hi) {
    asm("mov.b64 {%0, %1}, %2;" : "=f"(lo), "=f"(hi) : "l"(v));
}
__device__ __forceinline__ u64 fma2(u64 a, u64 b, u64 c) {
    u64 d; asm("fma.rn.f32x2 %0, %1, %2, %3;" : "=l"(d) : "l"(a), "l"(b), "l"(c)); return d;
}
__device__ __forceinline__ u64 add2(u64 a, u64 b) {
    u64 d; asm("add.rn.f32x2 %0, %1, %2;" : "=l"(d) : "l"(a), "l"(b)); return d;
}
__device__ __forceinline__ uint32_t smem_u32(const void* p) {
    uint32_t a;
    asm("{ .reg .u64 t; cvta.to.shared.u64 t, %1; cvt.u32.u64 %0, t; }" : "=r"(a) : "l"(p));
    return a;
}
__device__ __forceinline__ void bulk_g2s(uint32_t dst, const void* src, uint32_t bytes,
                                         uint32_t mbar) {
    asm volatile(
        "cp.async.bulk.shared::cluster.global.mbarrier::complete_tx::bytes [%0], [%1], %2, [%3];"
        :: "r"(dst), "l"(src), "r"(bytes), "r"(mbar) : "memory");
}
__device__ __forceinline__ void bulk_s2g(void* dst, uint32_t src, uint32_t bytes) {
    asm volatile("cp.async.bulk.global.shared::cta.bulk_group [%0], [%1], %2;"
                 :: "l"(dst), "r"(src), "r"(bytes) : "memory");
}

// ---------------------------------------------------------------------------
// Kernel 1: 256 blocks x 256 threads, 4 rows/block, one warp per (row, part).
// (unchanged from R9)
// ---------------------------------------------------------------------------
__global__ __launch_bounds__(256)
void precompute_rows(const float* __restrict__ gcn,
                     const float* __restrict__ wp,
                     const float* __restrict__ W,
                     const float* __restrict__ bias) {
    int t = threadIdx.x;
    int warp = t >> 5, lane = t & 31;
    int row = blockIdx.x * 4 + (warp >> 1);
    int part = warp & 1;
    const float* g = gcn + (size_t)row * D_;
    const float* Wb = W + part * 480;

    u64 acc[C_];
#pragma unroll
    for (int k = 0; k < C_; k++) acc[k] = 0ull;

#pragma unroll
    for (int it = 0; it < 3; it++) {
        int d = it * 128 + lane * 4;
        float4 gv = *reinterpret_cast<const float4*>(g + d);
        u64 gl = pack2(gv.x, gv.y), gh = pack2(gv.z, gv.w);
#pragma unroll
        for (int k = 0; k < C_; k++) {
            const float* wr = Wb + k * F_ + d;
            acc[k] = fma2(gl, *reinterpret_cast<const u64*>(wr), acc[k]);
            acc[k] = fma2(gh, *reinterpret_cast<const u64*>(wr + 2), acc[k]);
        }
    }
    if (lane < 24) {
        int d = 384 + lane * 4;
        float4 gv = *reinterpret_cast<const float4*>(g + d);
        u64 gl = pack2(gv.x, gv.y), gh = pack2(gv.z, gv.w);
#pragma unroll
        for (int k = 0; k < C_; k++) {
            const float* wr = Wb + k * F_ + d;
            acc[k] = fma2(gl, *reinterpret_cast<const u64*>(wr), acc[k]);
            acc[k] = fma2(gh, *reinterpret_cast<const u64*>(wr + 2), acc[k]);
        }
    }

    float s[C_];
#pragma unroll
    for (int k = 0; k < C_; k++) { float lo, hi; unpack2(acc[k], lo, hi); s[k] = lo + hi; }
#pragma unroll
    for (int k = 0; k < C_; k++)
#pragma unroll
        for (int off = 16; off > 0; off >>= 1)
            s[k] += __shfl_down_sync(0xffffffffu, s[k], off);

    if (lane == 0) {
        int b = row >> 7, si = row & (S_ - 1);
        const float* ed = wp + (((size_t)(b * S_ + si) * S_) + si) * E_;
        float e0[E_];
#pragma unroll
        for (int e = 0; e < E_; e++) e0[e] = ed[e];
        if (part == 0) {
#pragma unroll
            for (int k = 0; k < C_; k++) {
                float v = s[k];
#pragma unroll
                for (int e = 0; e < E_; e++) v += e0[e] * W[k * F_ + 960 + e];
                g_Cj[row * C_ + k] = v;
            }
        } else {
#pragma unroll
            for (int k = 0; k < C_; k++) {
                float v = s[k] + bias[k];
#pragma unroll
                for (int e = 0; e < E_; e++) v += e0[e] * W[k * F_ + 968 + e];
                g_Ci[row * C_ + k] = v;
            }
        }
    }
}

// ---------------------------------------------------------------------------
// Kernel 2: 512 blocks x 128 threads. Block = 2 (b,i) rows (bi0 even).
// TMA bulk-in: label(10240B) + wp(8192B) + Cj(5120B) + Ci(80B) -> smem, one
// mbarrier. Thread = (row r, column q): pixels (r,q) and (r,q+64), all 5
// channel pairs (each weight LDS feeds 2 pixels). Output staged in smem,
// TMA bulk-out. Global-side L1 wavefronts ~eliminated.
// ---------------------------------------------------------------------------
__global__ __launch_bounds__(128)
void combine_kernel(const float* __restrict__ label,
                    const float* __restrict__ wp,
                    const float* __restrict__ W,
                    float* __restrict__ out) {
    __shared__ __align__(128) float sLab[2 * S_ * C_];   // [r][j][c]
    __shared__ __align__(128) float sWp[2 * S_ * E_];    // [r][j][e]
    __shared__ __align__(128) float sCj[S_ * C_];        // [j][k]
    __shared__ __align__(128) float sOut[2 * S_ * C_];   // [r][j][c]
    __shared__ __align__(16)  float sCi[2 * C_];         // [r][k]
    __shared__ __align__(16)  u64 sWw[18][5];
    __shared__ __align__(8)   u64 mbar;

    int t = threadIdx.x;
    int bi0 = blockIdx.x * 2;
    int b = bi0 >> 7;
    int i0 = bi0 & (S_ - 1);

    uint32_t mb = smem_u32(&mbar);
    if (t == 0) {
        asm volatile("mbarrier.init.shared.b64 [%0], %1;" :: "r"(mb), "r"(1) : "memory");
    }
    __syncthreads();
    if (t == 0) {
        const uint32_t tx = 10240 + 8192 + 5120 + 80;
        asm volatile("mbarrier.arrive.expect_tx.shared.b64 _, [%0], %1;"
                     :: "r"(mb), "r"(tx) : "memory");
        bulk_g2s(smem_u32(sLab), label + (size_t)bi0 * S_ * C_, 10240, mb);
        bulk_g2s(smem_u32(sWp),  wp + (size_t)bi0 * S_ * E_,  8192, mb);
        bulk_g2s(smem_u32(sCj),  g_Cj + (size_t)b * S_ * C_,  5120, mb);
        bulk_g2s(smem_u32(sCi),  g_Ci + (size_t)bi0 * C_,       80, mb);
    }

    // stage epilogue weights while TMA is in flight
    if (t < 90) {
        int f = t / 5, h = t - 5 * f;
        int col = (f < 8) ? (976 + f) : (984 + (f - 8));
        sWw[f][h] = pack2(W[(2 * h) * F_ + col], W[(2 * h + 1) * F_ + col]);
    }
    __syncthreads();   // sWw visible to all

    // wait for TMA completion (phase 0)
    {
        uint32_t done;
        asm volatile(
            "{\n\t.reg .pred p;\n\t"
            "mbarrier.try_wait.parity.acquire.cta.shared::cta.b64 p, [%1], %2;\n\t"
            "selp.b32 %0, 1, 0, p;\n\t}"
            : "=r"(done) : "r"(mb), "r"(0) : "memory");
        if (!done) {
            asm volatile(
                "{\n\t.reg .pred P1;\n\t"
                "WL_%=:\n\t"
                "mbarrier.try_wait.parity.acquire.cta.shared::cta.b64 P1, [%0], %1, 0x989680;\n\t"
                "@P1 bra.uni WD_%=;\n\t"
                "bra.uni WL_%=;\n\t"
                "WD_%=:\n\t}"
                :: "r"(mb), "r"(0) : "memory");
        }
    }

    // ---- compute: thread = (r, q) -> pixels (r, q) and (r, q+64)
    int r = t >> 6;
    int q = t & 63;
    int i = i0 + r;
    int j0 = q, j1 = q + 64;

    float f0[18], f1[18];
    {
        const float4* w0 = reinterpret_cast<const float4*>(sWp + r * S_ * E_ + j0 * E_);
        const float4* w1 = reinterpret_cast<const float4*>(sWp + r * S_ * E_ + j1 * E_);
        float4 a = w0[0], c = w0[1];
        f0[0] = a.x; f0[1] = a.y; f0[2] = a.z; f0[3] = a.w;
        f0[4] = c.x; f0[5] = c.y; f0[6] = c.z; f0[7] = c.w;
        a = w1[0]; c = w1[1];
        f1[0] = a.x; f1[1] = a.y; f1[2] = a.z; f1[3] = a.w;
        f1[4] = c.x; f1[5] = c.y; f1[6] = c.z; f1[7] = c.w;
    }
    {
        const float* l0 = sLab + r * S_ * C_ + j0 * C_;
        const float* l1 = sLab + r * S_ * C_ + j1 * C_;
#pragma unroll
        for (int c = 0; c < C_; c++) { f0[8 + c] = l0[c]; f1[8 + c] = l1[c]; }
    }
    // masks: label ch 1..3 (f=9..11) kept when j>=i; ch 4..9 (f=12..17) when i>=j
    {
        float mu0 = (j0 >= i) ? 1.f : 0.f, ml0 = (i >= j0) ? 1.f : 0.f;
        float mu1 = (j1 >= i) ? 1.f : 0.f, ml1 = (i >= j1) ? 1.f : 0.f;
        f0[9] *= mu0; f0[10] *= mu0; f0[11] *= mu0;
        f1[9] *= mu1; f1[10] *= mu1; f1[11] *= mu1;
#pragma unroll
        for (int f = 12; f < 18; f++) { f0[f] *= ml0; f1[f] *= ml1; }
    }

    u64 A0[5], A1[5];
    {
        const u64* cj0 = reinterpret_cast<const u64*>(sCj + j0 * C_);
        const u64* cj1 = reinterpret_cast<const u64*>(sCj + j1 * C_);
        const u64* ci  = reinterpret_cast<const u64*>(sCi + r * C_);
#pragma unroll
        for (int h = 0; h < 5; h++) {
            u64 cv = ci[h];
            A0[h] = add2(cj0[h], cv);
            A1[h] = add2(cj1[h], cv);
        }
    }

#pragma unroll
    for (int f = 0; f < 18; f++) {
        u64 v0 = pack2(f0[f], f0[f]);
        u64 v1 = pack2(f1[f], f1[f]);
#pragma unroll
        for (int h = 0; h < 5; h++) {
            u64 w = sWw[f][h];               // one broadcast LDS.64, two uses
            A0[h] = fma2(v0, w, A0[h]);
            A1[h] = fma2(v1, w, A1[h]);
        }
    }

    {
        u64* o0 = reinterpret_cast<u64*>(sOut + r * S_ * C_ + j0 * C_);
        u64* o1 = reinterpret_cast<u64*>(sOut + r * S_ * C_ + j1 * C_);
#pragma unroll
        for (int h = 0; h < 5; h++) { o0[h] = A0[h]; o1[h] = A1[h]; }
    }
    __syncthreads();

    // TMA bulk-out
    if (t == 0) {
        asm volatile("fence.proxy.async.shared::cta;" ::: "memory");
        bulk_s2g(out + (size_t)bi0 * S_ * C_, smem_u32(sOut), 10240);
        asm volatile("cp.async.bulk.commit_group;" ::: "memory");
        asm volatile("cp.async.bulk.wait_group 0;" ::: "memory");
    }
}

extern "C" void kernel_launch(void* const* d_in, const int* in_sizes, int n_in,
                              void* d_out, int out_size) {
    const float* gcn   = (const float*)d_in[0];   // [8,128,480]
    const float* label = (const float*)d_in[1];   // [8,128,128,10]
    const float* wp    = (const float*)d_in[2];   // [8,128,128,8]
    // d_in[3] = tensor_masks (all ones, no effect on the reference math)
    const float* W     = (const float*)d_in[4];   // [10,994]
    const float* bias  = (const float*)d_in[5];   // [10]
    float* out = (float*)d_out;                   // [8,128,128,10]

    precompute_rows<<<B_ * S_ / 4, 256>>>(gcn, wp, W, bias);
    combine_kernel<<<B_ * S_ / 2, 128>>>(label, wp, W, out);
}